// round 15
// baseline (speedup 1.0000x reference)
#include <cuda_runtime.h>
#include <cuda_fp16.h>
#include <cstdint>
#include <math.h>

#define NB 16
#define NN 1024
#define DD 768
#define MM (NB * NN)

// ---------------- scratch ----------------
__device__ __half g_in_h[(size_t)MM * DD];
__device__ __half g_W7[(size_t)7 * DD * DD];   // Wfc, Wuy, Wux, Wry, Wrx, Wty, Wtx
__device__ __half g_fpT[(size_t)NB * DD * NN];
__device__ __half g_y[(size_t)MM * DD];
__device__ __half g_rx[(size_t)MM * DD];
__device__ float  g_u[(size_t)MM * DD];
__device__ __half g_E[(size_t)NB * NN * NN];
__device__ float  g_Z[MM];
__device__ float  g_q[MM], g_k[MM];
__device__ float  g_vq[DD], g_vk[DD], g_cqk[2];

// readiness counters (tile-granular producer/consumer sync)
__device__ int g_cntFp[96];    // [b*6 + dblock], target 8  (GEMM1 -> GEMM2)
__device__ int g_cntY[128];    // [mblock],       target 6  (GEMM2 -> gates/final)
__device__ int g_cntG[128];    // [mblock],       target 12 (gates -> final)

// ---------------- PDL helper ----------------
__device__ __forceinline__ void pdl_trigger() {
#if __CUDA_ARCH__ >= 900
    cudaTriggerProgrammaticLaunchCompletion();
#endif
}

// ---------------- counter helpers ----------------
// kinds: 1 = Fp (idx b*6+bx), 2 = Y (idx by), 3 = G (idx by)
__device__ __forceinline__ int* cnt_ptr(int kind, int bx, int by, int m0) {
    if (kind == 1) return &g_cntFp[(m0 >> 10) * 6 + bx];
    if (kind == 2) return &g_cntY[by];
    return &g_cntG[by];
}

__device__ __forceinline__ void wait_cnt(int* c, int target) {
    if (threadIdx.x == 0) {
        while (atomicAdd(c, 0) < target) __nanosleep(64);
    }
    __syncthreads();
}

// ---------------- cvt_main: in_h + Wfc (+ counter zeroing) ----------------
__global__ __launch_bounds__(256) void cvt_main_kernel(
    const float* __restrict__ inp, const float* __restrict__ wfc,
    __half* __restrict__ in_h, __half* __restrict__ W7)
{
    if (blockIdx.x == 0) {
        int t = threadIdx.x;
        if (t < 96) g_cntFp[t] = 0;
        if (t < 128) { g_cntY[t] = 0; g_cntG[t] = 0; }
    }
    const int inN4 = MM * DD / 4;
    const int wN4 = DD * DD / 4;
    int i = blockIdx.x * 256 + threadIdx.x;
    const float* src;
    __half* dst;
    int idx;
    if (i < inN4) {
        src = inp; dst = in_h; idx = i;
    } else {
        idx = i - inN4;
        if (idx >= wN4) return;
        src = wfc; dst = W7;
    }
    float4 v = ((const float4*)src)[idx];
    ((__half2*)dst)[idx * 2]     = __floats2half2_rn(v.x, v.y);
    ((__half2*)dst)[idx * 2 + 1] = __floats2half2_rn(v.z, v.w);
}

// ---------------- cvt_w6: the 6 gate weight matrices (side stream, after evJoinE) ----------------
__global__ __launch_bounds__(256) void cvt_w6_kernel(
    const float* __restrict__ w1, const float* __restrict__ w2,
    const float* __restrict__ w3, const float* __restrict__ w4,
    const float* __restrict__ w5, const float* __restrict__ w6,
    __half* __restrict__ W7)
{
    const float* srcs[6] = {w1, w2, w3, w4, w5, w6};
    const int wi = blockIdx.y;           // 0..5 -> W7 slots 1..6
    const int wN4 = DD * DD / 4;
    int idx = blockIdx.x * 256 + threadIdx.x;
    if (idx >= wN4) return;
    float4 v = ((const float4*)srcs[wi])[idx];
    __half2* d = (__half2*)(W7 + (size_t)(wi + 1) * DD * DD);
    d[idx * 2]     = __floats2half2_rn(v.x, v.y);
    d[idx * 2 + 1] = __floats2half2_rn(v.z, v.w);
}

// ---------------- vq/vk (blocks 0..2) + cqk (block 3) in one launch ----------------
__global__ __launch_bounds__(256) void vqk_kernel(
    const float* __restrict__ W_fc, const float* __restrict__ wq,
    const float* __restrict__ wk,
    const float* __restrict__ b_fc, const float* __restrict__ bq,
    const float* __restrict__ bk)
{
    if (blockIdx.x < 3) {
        int d = blockIdx.x * 256 + threadIdx.x;
        float sq = 0.0f, sk = 0.0f;
#pragma unroll 8
        for (int e = 0; e < DD; e++) {
            float w = W_fc[(size_t)e * DD + d];
            sq = fmaf(wq[e], w, sq);
            sk = fmaf(wk[e], w, sk);
        }
        g_vq[d] = sq;
        g_vk[d] = sk;
    } else {
        int tid = threadIdx.x;
        float sq = 0.0f, sk = 0.0f;
        for (int e = tid; e < DD; e += 256) {
            float b = b_fc[e];
            sq = fmaf(wq[e], b, sq);
            sk = fmaf(wk[e], b, sk);
        }
#pragma unroll
        for (int o = 16; o; o >>= 1) {
            sq += __shfl_down_sync(0xFFFFFFFFu, sq, o);
            sk += __shfl_down_sync(0xFFFFFFFFu, sk, o);
        }
        __shared__ float rq[8], rk[8];
        if ((tid & 31) == 0) { rq[tid >> 5] = sq; rk[tid >> 5] = sk; }
        __syncthreads();
        if (tid == 0) {
            float a = 0.0f, c = 0.0f;
#pragma unroll
            for (int w = 0; w < 8; w++) { a += rq[w]; c += rk[w]; }
            g_cqk[0] = a + bq[0];
            g_cqk[1] = c + bk[0];
        }
    }
}

// ---------------- q/k per-row dots (exact fp32) ----------------
__global__ __launch_bounds__(256) void qk_kernel(const float* __restrict__ inputs)
{
    const int m = blockIdx.x;
    const float* row = inputs + (size_t)m * DD;
    const int tid = threadIdx.x;
    float sq = 0.0f, sk = 0.0f;
    for (int d = tid; d < DD; d += 256) {
        float v = row[d];
        sq = fmaf(v, g_vq[d], sq);
        sk = fmaf(v, g_vk[d], sk);
    }
#pragma unroll
    for (int o = 16; o; o >>= 1) {
        sq += __shfl_down_sync(0xFFFFFFFFu, sq, o);
        sk += __shfl_down_sync(0xFFFFFFFFu, sk, o);
    }
    __shared__ float rq[8], rk[8];
    if ((tid & 31) == 0) { rq[tid >> 5] = sq; rk[tid >> 5] = sk; }
    __syncthreads();
    if (tid == 0) {
        float a = 0.0f, c = 0.0f;
#pragma unroll
        for (int w = 0; w < 8; w++) { a += rq[w]; c += rk[w]; }
        g_q[m] = a + g_cqk[0];
        g_k[m] = c + g_cqk[1];
    }
}

// ---------------- E = adj * exp(lrelu(q+k)) fp16 + exact row sums ----------------
__global__ __launch_bounds__(256) void maskexp_kernel(const float* __restrict__ adj)
{
    const int row = blockIdx.x;
    const int b = row >> 10;
    const float qi = g_q[row];
    const float* arow = adj + (size_t)row * NN;
    const float* kb = g_k + b * NN;
    __half* er = g_E + (size_t)row * NN;

    const int j4 = threadIdx.x;
    float4 a = ((const float4*)arow)[j4];
    float4 kv = ((const float4*)kb)[j4];
    float e[4];
    float vr[4] = {qi + kv.x, qi + kv.y, qi + kv.z, qi + kv.w};
    float ad[4] = {a.x, a.y, a.z, a.w};
#pragma unroll
    for (int t = 0; t < 4; t++) {
        float v = vr[t];
        float lr = v >= 0.0f ? v : 0.01f * v;
        e[t] = (ad[t] > 0.5f) ? __expf(lr) : 0.0f;
    }
    ((__half2*)er)[j4 * 2]     = __floats2half2_rn(e[0], e[1]);
    ((__half2*)er)[j4 * 2 + 1] = __floats2half2_rn(e[2], e[3]);

    float s = (e[0] + e[1]) + (e[2] + e[3]);
#pragma unroll
    for (int o = 16; o; o >>= 1) s += __shfl_down_sync(0xFFFFFFFFu, s, o);
    __shared__ float red[8];
    if ((threadIdx.x & 31) == 0) red[threadIdx.x >> 5] = s;
    __syncthreads();
    if (threadIdx.x == 0) {
        float t = 0.0f;
#pragma unroll
        for (int w = 0; w < 8; w++) t += red[w];
        g_Z[row] = t;
    }
}

// ================= fp16 1-pass MMA GEMM (PDL + counter sync, 3-stage) =================
#define TILE_B 16384
#define STAGE (2 * TILE_B)
#define NSTAGE 3

__device__ __forceinline__ uint32_t sw_off(int r, int c) {
    return (uint32_t)(r * 128 + ((c ^ (r & 7)) << 4));
}

__device__ __forceinline__ void ldsm4(uint32_t addr, uint32_t& r0, uint32_t& r1,
                                      uint32_t& r2, uint32_t& r3) {
    asm volatile("ldmatrix.sync.aligned.m8n8.x4.shared.b16 {%0,%1,%2,%3}, [%4];"
                 : "=r"(r0), "=r"(r1), "=r"(r2), "=r"(r3) : "r"(addr));
}

__device__ __forceinline__ void mma16(float* c, const uint32_t* a, const uint32_t* b) {
    asm volatile(
        "mma.sync.aligned.m16n8k16.row.col.f32.f16.f16.f32 "
        "{%0,%1,%2,%3}, {%4,%5,%6,%7}, {%8,%9}, {%0,%1,%2,%3};"
        : "+f"(c[0]), "+f"(c[1]), "+f"(c[2]), "+f"(c[3])
        : "r"(a[0]), "r"(a[1]), "r"(a[2]), "r"(a[3]), "r"(b[0]), "r"(b[1]));
}

__device__ __forceinline__ void cp16(char* smem_dst, const void* gsrc) {
    uint32_t s = (uint32_t)__cvta_generic_to_shared(smem_dst);
    asm volatile("cp.async.cg.shared.global [%0], [%1], 16;" :: "r"(s), "l"(gsrc));
}

// fast tanh via __expf; rel err ~1e-6
__device__ __forceinline__ float fast_tanh(float v) {
    float av = fabsf(v);
    float t = __expf(-2.0f * av);
    float th = __fdividef(1.0f - t, 1.0f + t);
    return copysignf(th, v);
}

__global__ __launch_bounds__(256, 2) void mma_gemm(
    const __half* __restrict__ A1, const __half* __restrict__ B1,
    const __half* __restrict__ A2, const __half* __restrict__ B2,
    const __half* __restrict__ B1b, const __half* __restrict__ B2b,
    const float* __restrict__ b1, const float* __restrict__ b2,
    const float* __restrict__ b1b, const float* __restrict__ b2b,
    const float* __restrict__ X, const float* __restrict__ U,
    const float* __restrict__ Zv,
    float* __restrict__ outF, __half* __restrict__ outH, __half* __restrict__ outH2,
    int K, int K1, int lda, int ldb, size_t bstrideB, int mode,
    int rot,
    int w0_kind, int w0_target,
    int wB_pos, int wB_kind, int wB_target,
    int prod_kind)
{
    extern __shared__ char smem[];

    pdl_trigger();

    const int tid = threadIdx.x;
    const int lane = tid & 31;
    const int warp = tid >> 5;
    const int wy = warp >> 1;
    const int wx = warp & 1;
    const int m0 = blockIdx.y * 128;
    const int n0 = blockIdx.x * 128;

    const __half* Bw1 = B1;
    const __half* Bw2 = B2;
    const float* bb1 = b1;
    const float* bb2 = b2;
    int md = mode;
    if (mode == 5) {
        if (blockIdx.z == 1) { Bw1 = B1b; Bw2 = B2b; bb1 = b1b; bb2 = b2b; md = 2; }
        else md = 1;
    }

    const size_t bOffB = (size_t)(m0 >> 10) * bstrideB;

    const int lr = tid >> 1;
    const int lc4 = (tid & 1) * 4;

    float acc[2][8][4];
#pragma unroll
    for (int mt = 0; mt < 2; mt++)
#pragma unroll
        for (int nt = 0; nt < 8; nt++)
#pragma unroll
            for (int v = 0; v < 4; v++) acc[mt][nt][v] = 0.0f;

    const int NT = K / 64;

    auto load_tile = [&](int ktp, int st) {
        int kb = ktp * 64;
        const __half *A, *B;
        int ko;
        if (kb < K1) { A = A1; B = Bw1; ko = kb; }
        else         { A = A2; B = Bw2; ko = kb - K1; }
        char* base = smem + st * STAGE;
        size_t abase = (size_t)(m0 + lr) * lda + ko;
        size_t bbase = bOffB + (size_t)(n0 + lr) * ldb + ko;
#pragma unroll
        for (int c = 0; c < 4; c++) {
            int ch = lc4 + c;
            uint32_t so = sw_off(lr, ch);
            cp16(base + so,          A + abase + ch * 8);
            cp16(base + TILE_B + so, B + bbase + ch * 8);
        }
    };
    auto phys = [&](int pos) { int p = pos + rot; return p >= NT ? p - NT : p; };

    // prologue: tiles 0,1
    if (w0_kind) wait_cnt(cnt_ptr(w0_kind, blockIdx.x, blockIdx.y, m0), w0_target);
    load_tile(phys(0), 0);
    asm volatile("cp.async.commit_group;");
    if (NT > 1) load_tile(phys(1), 1);
    asm volatile("cp.async.commit_group;");

    for (int kt = 0; kt < NT; kt++) {
        asm volatile("cp.async.wait_group 1;");
        __syncthreads();
        if (kt + 2 < NT) {
            if (kt + 2 == wB_pos)
                wait_cnt(cnt_ptr(wB_kind, blockIdx.x, blockIdx.y, m0), wB_target);
            load_tile(phys(kt + 2), (kt + 2) % NSTAGE);
        }
        asm volatile("cp.async.commit_group;");

        char* As = smem + (kt % NSTAGE) * STAGE;
        char* Bs = As + TILE_B;

#pragma unroll
        for (int ks = 0; ks < 4; ks++) {
            uint32_t ah[2][4], bh[8][2];
#pragma unroll
            for (int mt = 0; mt < 2; mt++) {
                int r = wy * 32 + mt * 16 + (lane & 15);
                int ch = ks * 2 + (lane >> 4);
                uint32_t so = sw_off(r, ch);
                ldsm4((uint32_t)__cvta_generic_to_shared(As + so),
                      ah[mt][0], ah[mt][1], ah[mt][2], ah[mt][3]);
            }
#pragma unroll
            for (int np = 0; np < 4; np++) {
                int r = wx * 64 + np * 16 + (lane & 7) + ((lane >> 4) << 3);
                int ch = ks * 2 + ((lane >> 3) & 1);
                uint32_t so = sw_off(r, ch);
                ldsm4((uint32_t)__cvta_generic_to_shared(Bs + so),
                      bh[np * 2][0], bh[np * 2][1], bh[np * 2 + 1][0], bh[np * 2 + 1][1]);
            }
#pragma unroll
            for (int mt = 0; mt < 2; mt++)
#pragma unroll
                for (int nt = 0; nt < 8; nt++)
                    mma16(acc[mt][nt], ah[mt], bh[nt]);
        }
    }

    // ---------------- epilogue ----------------
    if (md == 0) {
        __syncthreads();   // smem reuse for transpose
        __half* T = (__half*)smem + warp * (64 * 34);
#pragma unroll
        for (int mt = 0; mt < 2; mt++) {
#pragma unroll
            for (int nt = 0; nt < 8; nt++) {
                int c0l = nt * 8 + (lane & 3) * 2;
                int cg = n0 + wx * 64 + c0l;
                float* ac = acc[mt][nt];
#pragma unroll
                for (int h = 0; h < 2; h++) {
                    int rr = mt * 16 + (lane >> 2) + h * 8;
                    T[c0l * 34 + rr]       = __float2half(ac[h * 2]     + bb1[cg]);
                    T[(c0l + 1) * 34 + rr] = __float2half(ac[h * 2 + 1] + bb1[cg + 1]);
                }
            }
        }
        __syncwarp();
        const int bb = m0 >> 10;
        const int jj0 = (m0 & 1023) + wy * 32;
#pragma unroll
        for (int cp = 0; cp < 2; cp++) {
            int c = lane + cp * 32;
            const uint32_t* src = (const uint32_t*)(T + c * 34);
            uint32_t w4[16];
#pragma unroll
            for (int i = 0; i < 16; i++) w4[i] = src[i];
            size_t g = ((size_t)bb * DD + (n0 + wx * 64 + c)) * NN + jj0;
            uint4* dst = (uint4*)(outH + g);
            dst[0] = make_uint4(w4[0],  w4[1],  w4[2],  w4[3]);
            dst[1] = make_uint4(w4[4],  w4[5],  w4[6],  w4[7]);
            dst[2] = make_uint4(w4[8],  w4[9],  w4[10], w4[11]);
            dst[3] = make_uint4(w4[12], w4[13], w4[14], w4[15]);
        }
    } else {
        const int mbase = m0 + wy * 32;
        const int nbase = n0 + wx * 64;
#pragma unroll
        for (int mt = 0; mt < 2; mt++) {
#pragma unroll
            for (int nt = 0; nt < 8; nt++) {
                int c0 = nbase + nt * 8 + (lane & 3) * 2;
                int r0 = mbase + mt * 16 + (lane >> 2);
                float* ac = acc[mt][nt];
#pragma unroll
                for (int h = 0; h < 2; h++) {
                    int r = r0 + h * 8;
                    float v0 = ac[h * 2], v1 = ac[h * 2 + 1];
                    size_t off = (size_t)r * DD + c0;
                    if (md == 4) {
                        float zr = 1.0f / Zv[r];
                        *(__half2*)(outH + off) = __floats2half2_rn(v0 * zr, v1 * zr);
                    } else if (md == 1) {
                        v0 += bb1[c0] + bb2[c0];
                        v1 += bb1[c0 + 1] + bb2[c0 + 1];
                        float s0 = 1.0f / (1.0f + __expf(-v0));
                        float s1 = 1.0f / (1.0f + __expf(-v1));
                        *(float2*)(outF + off) = make_float2(s0, s1);
                    } else if (md == 2) {
                        v0 += bb1[c0] + bb2[c0];
                        v1 += bb1[c0 + 1] + bb2[c0 + 1];
                        float s0 = (1.0f / (1.0f + __expf(-v0))) * X[off];
                        float s1 = (1.0f / (1.0f + __expf(-v1))) * X[off + 1];
                        *(__half2*)(outH2 + off) = __floats2half2_rn(s0, s1);
                    } else {
                        v0 += bb1[c0] + bb2[c0];
                        v1 += bb1[c0 + 1] + bb2[c0 + 1];
                        float t0 = fast_tanh(v0), t1 = fast_tanh(v1);
                        float u0 = U[off], u1 = U[off + 1];
                        float x0 = X[off], x1 = X[off + 1];
                        *(float2*)(outF + off) =
                            make_float2(x0 + u0 * (t0 - x0), x1 + u1 * (t1 - x1));
                    }
                }
            }
        }
    }

    // ---------------- producer signal ----------------
    if (prod_kind) {
        __syncthreads();
        __threadfence();
        if (tid == 0)
            atomicAdd(cnt_ptr(prod_kind, blockIdx.x, blockIdx.y, m0), 1);
    }
}

// ---------------- launch ----------------
extern "C" void kernel_launch(void* const* d_in, const int* in_sizes, int n_in,
                              void* d_out, int out_size)
{
    const float* inputs = (const float*)d_in[0];
    const float* adj    = (const float*)d_in[1];
    const float* W_fc   = (const float*)d_in[2];
    const float* b_fc   = (const float*)d_in[3];
    const float* w_q    = (const float*)d_in[4];
    const float* b_q    = (const float*)d_in[5];
    const float* w_k    = (const float*)d_in[6];
    const float* b_k    = (const float*)d_in[7];
    const float* W_uy   = (const float*)d_in[8];
    const float* b_uy   = (const float*)d_in[9];
    const float* W_ux   = (const float*)d_in[10];
    const float* b_ux   = (const float*)d_in[11];
    const float* W_ry   = (const float*)d_in[12];
    const float* b_ry   = (const float*)d_in[13];
    const float* W_rx   = (const float*)d_in[14];
    const float* b_rx   = (const float*)d_in[15];
    const float* W_ty   = (const float*)d_in[16];
    const float* b_ty   = (const float*)d_in[17];
    const float* W_tx   = (const float*)d_in[18];
    const float* b_tx   = (const float*)d_in[19];
    float* out = (float*)d_out;

    __half *in_h, *W7, *fpT, *y, *rx, *E;
    float *u, *Z;
    cudaGetSymbolAddress((void**)&in_h, g_in_h);
    cudaGetSymbolAddress((void**)&W7, g_W7);
    cudaGetSymbolAddress((void**)&fpT, g_fpT);
    cudaGetSymbolAddress((void**)&y, g_y);
    cudaGetSymbolAddress((void**)&rx, g_rx);
    cudaGetSymbolAddress((void**)&u, g_u);
    cudaGetSymbolAddress((void**)&E, g_E);
    cudaGetSymbolAddress((void**)&Z, g_Z);

    const int WSZ = DD * DD;
    const size_t smem = NSTAGE * STAGE;   // 96KB
    cudaFuncSetAttribute(mma_gemm, cudaFuncAttributeMaxDynamicSharedMemorySize, (int)smem);

    static cudaStream_t s2 = nullptr;
    static cudaEvent_t evFork = nullptr, evJoinE = nullptr, evJoinW = nullptr;
    if (!s2) {
        cudaStreamCreateWithFlags(&s2, cudaStreamNonBlocking);
        cudaEventCreateWithFlags(&evFork, cudaEventDisableTiming);
        cudaEventCreateWithFlags(&evJoinE, cudaEventDisableTiming);
        cudaEventCreateWithFlags(&evJoinW, cudaEventDisableTiming);
    }

    // ---- fork: q/k/E chain, then gate-weight converts, on s2 ----
    cudaEventRecord(evFork, 0);
    cudaStreamWaitEvent(s2, evFork, 0);
    vqk_kernel<<<4, 256, 0, s2>>>(W_fc, w_q, w_k, b_fc, b_q, b_k);
    qk_kernel<<<MM, 256, 0, s2>>>(inputs);
    maskexp_kernel<<<MM, 256, 0, s2>>>(adj);
    cudaEventRecord(evJoinE, s2);     // E/Z ready (GEMM2's dependency)
    cvt_w6_kernel<<<dim3((WSZ / 4 + 255) / 256, 6), 256, 0, s2>>>(
        W_uy, W_ux, W_ry, W_rx, W_ty, W_tx, W7);
    cudaEventRecord(evJoinW, s2);     // gate weights ready (gates' dependency)

    // ---- main stream: cvt_main (in_h + Wfc + counter zeroing) ----
    {
        int totalN4 = MM * DD / 4 + WSZ / 4;
        cvt_main_kernel<<<(totalN4 + 255) / 256, 256>>>(inputs, W_fc, in_h, W7);
    }
    __half* Wfc_h = W7;
    __half* Wuy_h = W7 + (size_t)1 * WSZ;
    __half* Wux_h = W7 + (size_t)2 * WSZ;
    __half* Wry_h = W7 + (size_t)3 * WSZ;
    __half* Wrx_h = W7 + (size_t)4 * WSZ;
    __half* Wty_h = W7 + (size_t)5 * WSZ;
    __half* Wtx_h = W7 + (size_t)6 * WSZ;

    dim3 grid(DD / 128, MM / 128);       // (6, 128)
    dim3 gridZ(DD / 128, MM / 128, 2);   // merged u+rx

    cudaLaunchAttribute pdlAttr[1];
    pdlAttr[0].id = cudaLaunchAttributeProgrammaticStreamSerialization;
    pdlAttr[0].val.programmaticStreamSerializationAllowed = 1;

    auto launch_gemm = [&](dim3 g,
                           const __half* A1, const __half* B1,
                           const __half* A2, const __half* B2,
                           const __half* B1b, const __half* B2b,
                           const float* b1, const float* b2,
                           const float* b1b, const float* b2b,
                           const float* X, const float* U, const float* Zv,
                           float* outF, __half* outH, __half* outH2,
                           int K, int K1, int lda, int ldb, size_t bstrideB,
                           int mode, int rot,
                           int w0k, int w0t, int wBp, int wBk, int wBt, int prod) {
        cudaLaunchConfig_t cfg = {};
        cfg.gridDim = g;
        cfg.blockDim = dim3(256, 1, 1);
        cfg.dynamicSmemBytes = smem;
        cfg.stream = 0;
        cfg.attrs = pdlAttr;
        cfg.numAttrs = 1;
        cudaLaunchKernelEx(&cfg, mma_gemm,
                           A1, B1, A2, B2, B1b, B2b, b1, b2, b1b, b2b,
                           X, U, Zv, outF, outH, outH2,
                           K, K1, lda, ldb, bstrideB, mode, rot,
                           w0k, w0t, wBp, wBk, wBt, prod);
    };

    // 1) feat_proj -> fpT. PDL fallback = waits cvt_main completion; signals cntFp.
    launch_gemm(grid,
                in_h, Wfc_h, in_h, Wfc_h, nullptr, nullptr,
                b_fc, nullptr, nullptr, nullptr,
                nullptr, nullptr, nullptr,
                nullptr, fpT, nullptr,
                DD, DD, DD, DD, 0, 0, 0,
                0, 0, -1, 0, 0, 1);

    // ---- join E: GEMM2 needs E/Z only ----
    cudaStreamWaitEvent(0, evJoinE, 0);

    // 2) y = (E @ fpT^T)/Z. Waits its 8 fpT producers (cntFp) at pos 0; signals cntY.
    launch_gemm(grid,
                E, fpT, E, fpT, nullptr, nullptr,
                nullptr, nullptr, nullptr, nullptr,
                nullptr, nullptr, Z,
                nullptr, y, nullptr,
                NN, NN, NN, NN, (size_t)DD * NN, 4, 0,
                1, 8, -1, 0, 0, 2);

    // ---- join W: gates need the 6 gate weight matrices ----
    cudaStreamWaitEvent(0, evJoinW, 0);

    // 3+4) merged gates. rot=12: x-half (tiles 12..23) first; waits cntY[mb]==6
    //      before y-half at pos 12; signals cntG.
    launch_gemm(gridZ,
                y, Wuy_h, in_h, Wux_h, Wry_h, Wrx_h,
                b_uy, b_ux, b_ry, b_rx,
                inputs, nullptr, nullptr,
                u, nullptr, rx,
                2 * DD, DD, DD, DD, 0, 5, 12,
                0, 0, 12, 2, 6, 3);

    // 5) final. y-half first after cntY[mb]==6; waits cntG[mb]==12 at pos 12.
    launch_gemm(grid,
                y, Wty_h, rx, Wtx_h, nullptr, nullptr,
                b_ty, b_tx, nullptr, nullptr,
                inputs, u, nullptr,
                out, nullptr, nullptr,
                2 * DD, DD, DD, DD, 0, 3, 0,
                2, 6, 12, 3, 12, 0);
}

// round 16
// speedup vs baseline: 1.0338x; 1.0338x over previous
#include <cuda_runtime.h>
#include <cuda_fp16.h>
#include <cstdint>
#include <math.h>

#define NB 16
#define NN 1024
#define DD 768
#define MM (NB * NN)

// ---------------- scratch ----------------
__device__ __half g_in_h[(size_t)MM * DD];
__device__ __half g_W7[(size_t)7 * DD * DD];   // Wfc, Wuy, Wux, Wry, Wrx, Wty, Wtx
__device__ __half g_fpT[(size_t)NB * DD * NN];
__device__ __half g_y[(size_t)MM * DD];
__device__ __half g_rx[(size_t)MM * DD];
__device__ float  g_u[(size_t)MM * DD];
__device__ __half g_E[(size_t)NB * NN * NN];
__device__ float  g_Z[MM];
__device__ float  g_q[MM], g_k[MM];
__device__ float  g_vq[DD], g_vk[DD], g_cqk[2];

// readiness counters (tile-granular producer/consumer sync)
__device__ int g_cntFp[96];    // [b*6 + dblock], target 8  (GEMM1 -> GEMM2)
__device__ int g_cntY[128];    // [mblock],       target 6  (GEMM2 -> gates/final)
__device__ int g_cntG[128];    // [mblock],       target 12 (gates -> final)

// ---------------- PDL helper ----------------
__device__ __forceinline__ void pdl_trigger() {
#if __CUDA_ARCH__ >= 900
    cudaTriggerProgrammaticLaunchCompletion();
#endif
}

// ---------------- counter helpers ----------------
// kinds: 1 = Fp (idx b*6+bx), 2 = Y (idx by), 3 = G (idx by)
__device__ __forceinline__ int* cnt_ptr(int kind, int bx, int by, int m0) {
    if (kind == 1) return &g_cntFp[(m0 >> 10) * 6 + bx];
    if (kind == 2) return &g_cntY[by];
    return &g_cntG[by];
}

__device__ __forceinline__ void wait_cnt(int* c, int target) {
    if (threadIdx.x == 0) {
        while (atomicAdd(c, 0) < target) __nanosleep(64);
    }
    __syncthreads();
}

// ---------------- all fp32->fp16 converts in ONE launch (+ counter zeroing) ----------------
__global__ __launch_bounds__(256) void cvt_all_kernel(
    const float* __restrict__ inp,
    const float* __restrict__ w0, const float* __restrict__ w1,
    const float* __restrict__ w2, const float* __restrict__ w3,
    const float* __restrict__ w4, const float* __restrict__ w5,
    const float* __restrict__ w6,
    __half* __restrict__ in_h, __half* __restrict__ W7)
{
    if (blockIdx.x == 0) {
        int t = threadIdx.x;
        if (t < 96) g_cntFp[t] = 0;
        if (t < 128) { g_cntY[t] = 0; g_cntG[t] = 0; }
    }
    const int inN4 = MM * DD / 4;
    const int wN4 = DD * DD / 4;
    int i = blockIdx.x * 256 + threadIdx.x;
    const float* src;
    __half* dst;
    int idx;
    if (i < inN4) {
        src = inp; dst = in_h; idx = i;
    } else {
        int j = i - inN4;
        if (j >= 7 * wN4) return;
        int wi = j / wN4;
        idx = j - wi * wN4;
        switch (wi) {
            case 0: src = w0; break;
            case 1: src = w1; break;
            case 2: src = w2; break;
            case 3: src = w3; break;
            case 4: src = w4; break;
            case 5: src = w5; break;
            default: src = w6; break;
        }
        dst = W7 + (size_t)wi * DD * DD;
    }
    float4 v = ((const float4*)src)[idx];
    ((__half2*)dst)[idx * 2]     = __floats2half2_rn(v.x, v.y);
    ((__half2*)dst)[idx * 2 + 1] = __floats2half2_rn(v.z, v.w);
}

// ---------------- vq/vk (blocks 0..2) + cqk (block 3) in one launch ----------------
__global__ __launch_bounds__(256) void vqk_kernel(
    const float* __restrict__ W_fc, const float* __restrict__ wq,
    const float* __restrict__ wk,
    const float* __restrict__ b_fc, const float* __restrict__ bq,
    const float* __restrict__ bk)
{
    if (blockIdx.x < 3) {
        int d = blockIdx.x * 256 + threadIdx.x;
        float sq = 0.0f, sk = 0.0f;
#pragma unroll 8
        for (int e = 0; e < DD; e++) {
            float w = W_fc[(size_t)e * DD + d];
            sq = fmaf(wq[e], w, sq);
            sk = fmaf(wk[e], w, sk);
        }
        g_vq[d] = sq;
        g_vk[d] = sk;
    } else {
        int tid = threadIdx.x;
        float sq = 0.0f, sk = 0.0f;
        for (int e = tid; e < DD; e += 256) {
            float b = b_fc[e];
            sq = fmaf(wq[e], b, sq);
            sk = fmaf(wk[e], b, sk);
        }
#pragma unroll
        for (int o = 16; o; o >>= 1) {
            sq += __shfl_down_sync(0xFFFFFFFFu, sq, o);
            sk += __shfl_down_sync(0xFFFFFFFFu, sk, o);
        }
        __shared__ float rq[8], rk[8];
        if ((tid & 31) == 0) { rq[tid >> 5] = sq; rk[tid >> 5] = sk; }
        __syncthreads();
        if (tid == 0) {
            float a = 0.0f, c = 0.0f;
#pragma unroll
            for (int w = 0; w < 8; w++) { a += rq[w]; c += rk[w]; }
            g_cqk[0] = a + bq[0];
            g_cqk[1] = c + bk[0];
        }
    }
}

// ---------------- q/k per-row dots (exact fp32) ----------------
__global__ __launch_bounds__(256) void qk_kernel(const float* __restrict__ inputs)
{
    const int m = blockIdx.x;
    const float* row = inputs + (size_t)m * DD;
    const int tid = threadIdx.x;
    float sq = 0.0f, sk = 0.0f;
    for (int d = tid; d < DD; d += 256) {
        float v = row[d];
        sq = fmaf(v, g_vq[d], sq);
        sk = fmaf(v, g_vk[d], sk);
    }
#pragma unroll
    for (int o = 16; o; o >>= 1) {
        sq += __shfl_down_sync(0xFFFFFFFFu, sq, o);
        sk += __shfl_down_sync(0xFFFFFFFFu, sk, o);
    }
    __shared__ float rq[8], rk[8];
    if ((tid & 31) == 0) { rq[tid >> 5] = sq; rk[tid >> 5] = sk; }
    __syncthreads();
    if (tid == 0) {
        float a = 0.0f, c = 0.0f;
#pragma unroll
        for (int w = 0; w < 8; w++) { a += rq[w]; c += rk[w]; }
        g_q[m] = a + g_cqk[0];
        g_k[m] = c + g_cqk[1];
    }
}

// ---------------- E = adj * exp(lrelu(q+k)) fp16 + exact row sums ----------------
__global__ __launch_bounds__(256) void maskexp_kernel(const float* __restrict__ adj)
{
    const int row = blockIdx.x;
    const int b = row >> 10;
    const float qi = g_q[row];
    const float* arow = adj + (size_t)row * NN;
    const float* kb = g_k + b * NN;
    __half* er = g_E + (size_t)row * NN;

    const int j4 = threadIdx.x;
    float4 a = ((const float4*)arow)[j4];
    float4 kv = ((const float4*)kb)[j4];
    float e[4];
    float vr[4] = {qi + kv.x, qi + kv.y, qi + kv.z, qi + kv.w};
    float ad[4] = {a.x, a.y, a.z, a.w};
#pragma unroll
    for (int t = 0; t < 4; t++) {
        float v = vr[t];
        float lr = v >= 0.0f ? v : 0.01f * v;
        e[t] = (ad[t] > 0.5f) ? __expf(lr) : 0.0f;
    }
    ((__half2*)er)[j4 * 2]     = __floats2half2_rn(e[0], e[1]);
    ((__half2*)er)[j4 * 2 + 1] = __floats2half2_rn(e[2], e[3]);

    float s = (e[0] + e[1]) + (e[2] + e[3]);
#pragma unroll
    for (int o = 16; o; o >>= 1) s += __shfl_down_sync(0xFFFFFFFFu, s, o);
    __shared__ float red[8];
    if ((threadIdx.x & 31) == 0) red[threadIdx.x >> 5] = s;
    __syncthreads();
    if (threadIdx.x == 0) {
        float t = 0.0f;
#pragma unroll
        for (int w = 0; w < 8; w++) t += red[w];
        g_Z[row] = t;
    }
}

// ================= fp16 1-pass MMA GEMM (PDL + counter sync, 3-stage) =================
#define TILE_B 16384
#define STAGE (2 * TILE_B)
#define NSTAGE 3

__device__ __forceinline__ uint32_t sw_off(int r, int c) {
    return (uint32_t)(r * 128 + ((c ^ (r & 7)) << 4));
}

__device__ __forceinline__ void ldsm4(uint32_t addr, uint32_t& r0, uint32_t& r1,
                                      uint32_t& r2, uint32_t& r3) {
    asm volatile("ldmatrix.sync.aligned.m8n8.x4.shared.b16 {%0,%1,%2,%3}, [%4];"
                 : "=r"(r0), "=r"(r1), "=r"(r2), "=r"(r3) : "r"(addr));
}

__device__ __forceinline__ void mma16(float* c, const uint32_t* a, const uint32_t* b) {
    asm volatile(
        "mma.sync.aligned.m16n8k16.row.col.f32.f16.f16.f32 "
        "{%0,%1,%2,%3}, {%4,%5,%6,%7}, {%8,%9}, {%0,%1,%2,%3};"
        : "+f"(c[0]), "+f"(c[1]), "+f"(c[2]), "+f"(c[3])
        : "r"(a[0]), "r"(a[1]), "r"(a[2]), "r"(a[3]), "r"(b[0]), "r"(b[1]));
}

__device__ __forceinline__ void cp16(char* smem_dst, const void* gsrc) {
    uint32_t s = (uint32_t)__cvta_generic_to_shared(smem_dst);
    asm volatile("cp.async.cg.shared.global [%0], [%1], 16;" :: "r"(s), "l"(gsrc));
}

// fast tanh via __expf; rel err ~1e-6
__device__ __forceinline__ float fast_tanh(float v) {
    float av = fabsf(v);
    float t = __expf(-2.0f * av);
    float th = __fdividef(1.0f - t, 1.0f + t);
    return copysignf(th, v);
}

__global__ __launch_bounds__(256, 2) void mma_gemm(
    const __half* __restrict__ A1, const __half* __restrict__ B1,
    const __half* __restrict__ A2, const __half* __restrict__ B2,
    const __half* __restrict__ B1b, const __half* __restrict__ B2b,
    const float* __restrict__ b1, const float* __restrict__ b2,
    const float* __restrict__ b1b, const float* __restrict__ b2b,
    const float* __restrict__ X, const float* __restrict__ U,
    const float* __restrict__ Zv,
    float* __restrict__ outF, __half* __restrict__ outH, __half* __restrict__ outH2,
    int K, int K1, int lda, int ldb, size_t bstrideB, int mode,
    int rot,
    int w0_kind, int w0_target,
    int wB_pos, int wB_kind, int wB_target,
    int prod_kind)
{
    extern __shared__ char smem[];

    pdl_trigger();

    const int tid = threadIdx.x;
    const int lane = tid & 31;
    const int warp = tid >> 5;
    const int wy = warp >> 1;
    const int wx = warp & 1;
    const int m0 = blockIdx.y * 128;
    const int n0 = blockIdx.x * 128;

    const __half* Bw1 = B1;
    const __half* Bw2 = B2;
    const float* bb1 = b1;
    const float* bb2 = b2;
    int md = mode;
    if (mode == 5) {
        if (blockIdx.z == 1) { Bw1 = B1b; Bw2 = B2b; bb1 = b1b; bb2 = b2b; md = 2; }
        else md = 1;
    }

    const size_t bOffB = (size_t)(m0 >> 10) * bstrideB;

    const int lr = tid >> 1;
    const int lc4 = (tid & 1) * 4;

    float acc[2][8][4];
#pragma unroll
    for (int mt = 0; mt < 2; mt++)
#pragma unroll
        for (int nt = 0; nt < 8; nt++)
#pragma unroll
            for (int v = 0; v < 4; v++) acc[mt][nt][v] = 0.0f;

    const int NT = K / 64;

    auto load_tile = [&](int ktp, int st) {
        int kb = ktp * 64;
        const __half *A, *B;
        int ko;
        if (kb < K1) { A = A1; B = Bw1; ko = kb; }
        else         { A = A2; B = Bw2; ko = kb - K1; }
        char* base = smem + st * STAGE;
        size_t abase = (size_t)(m0 + lr) * lda + ko;
        size_t bbase = bOffB + (size_t)(n0 + lr) * ldb + ko;
#pragma unroll
        for (int c = 0; c < 4; c++) {
            int ch = lc4 + c;
            uint32_t so = sw_off(lr, ch);
            cp16(base + so,          A + abase + ch * 8);
            cp16(base + TILE_B + so, B + bbase + ch * 8);
        }
    };
    auto phys = [&](int pos) { int p = pos + rot; return p >= NT ? p - NT : p; };

    // prologue: tiles 0,1
    if (w0_kind) wait_cnt(cnt_ptr(w0_kind, blockIdx.x, blockIdx.y, m0), w0_target);
    load_tile(phys(0), 0);
    asm volatile("cp.async.commit_group;");
    if (NT > 1) load_tile(phys(1), 1);
    asm volatile("cp.async.commit_group;");

    for (int kt = 0; kt < NT; kt++) {
        asm volatile("cp.async.wait_group 1;");
        __syncthreads();
        if (kt + 2 < NT) {
            if (kt + 2 == wB_pos)
                wait_cnt(cnt_ptr(wB_kind, blockIdx.x, blockIdx.y, m0), wB_target);
            load_tile(phys(kt + 2), (kt + 2) % NSTAGE);
        }
        asm volatile("cp.async.commit_group;");

        char* As = smem + (kt % NSTAGE) * STAGE;
        char* Bs = As + TILE_B;

#pragma unroll
        for (int ks = 0; ks < 4; ks++) {
            uint32_t ah[2][4], bh[8][2];
#pragma unroll
            for (int mt = 0; mt < 2; mt++) {
                int r = wy * 32 + mt * 16 + (lane & 15);
                int ch = ks * 2 + (lane >> 4);
                uint32_t so = sw_off(r, ch);
                ldsm4((uint32_t)__cvta_generic_to_shared(As + so),
                      ah[mt][0], ah[mt][1], ah[mt][2], ah[mt][3]);
            }
#pragma unroll
            for (int np = 0; np < 4; np++) {
                int r = wx * 64 + np * 16 + (lane & 7) + ((lane >> 4) << 3);
                int ch = ks * 2 + ((lane >> 3) & 1);
                uint32_t so = sw_off(r, ch);
                ldsm4((uint32_t)__cvta_generic_to_shared(Bs + so),
                      bh[np * 2][0], bh[np * 2][1], bh[np * 2 + 1][0], bh[np * 2 + 1][1]);
            }
#pragma unroll
            for (int mt = 0; mt < 2; mt++)
#pragma unroll
                for (int nt = 0; nt < 8; nt++)
                    mma16(acc[mt][nt], ah[mt], bh[nt]);
        }
    }

    // ---------------- epilogue ----------------
    if (md == 0) {
        __syncthreads();   // smem reuse for transpose
        __half* T = (__half*)smem + warp * (64 * 34);
#pragma unroll
        for (int mt = 0; mt < 2; mt++) {
#pragma unroll
            for (int nt = 0; nt < 8; nt++) {
                int c0l = nt * 8 + (lane & 3) * 2;
                int cg = n0 + wx * 64 + c0l;
                float* ac = acc[mt][nt];
#pragma unroll
                for (int h = 0; h < 2; h++) {
                    int rr = mt * 16 + (lane >> 2) + h * 8;
                    T[c0l * 34 + rr]       = __float2half(ac[h * 2]     + bb1[cg]);
                    T[(c0l + 1) * 34 + rr] = __float2half(ac[h * 2 + 1] + bb1[cg + 1]);
                }
            }
        }
        __syncwarp();
        const int bb = m0 >> 10;
        const int jj0 = (m0 & 1023) + wy * 32;
#pragma unroll
        for (int cp = 0; cp < 2; cp++) {
            int c = lane + cp * 32;
            const uint32_t* src = (const uint32_t*)(T + c * 34);
            uint32_t w4[16];
#pragma unroll
            for (int i = 0; i < 16; i++) w4[i] = src[i];
            size_t g = ((size_t)bb * DD + (n0 + wx * 64 + c)) * NN + jj0;
            uint4* dst = (uint4*)(outH + g);
            dst[0] = make_uint4(w4[0],  w4[1],  w4[2],  w4[3]);
            dst[1] = make_uint4(w4[4],  w4[5],  w4[6],  w4[7]);
            dst[2] = make_uint4(w4[8],  w4[9],  w4[10], w4[11]);
            dst[3] = make_uint4(w4[12], w4[13], w4[14], w4[15]);
        }
    } else {
        const int mbase = m0 + wy * 32;
        const int nbase = n0 + wx * 64;
#pragma unroll
        for (int mt = 0; mt < 2; mt++) {
#pragma unroll
            for (int nt = 0; nt < 8; nt++) {
                int c0 = nbase + nt * 8 + (lane & 3) * 2;
                int r0 = mbase + mt * 16 + (lane >> 2);
                float* ac = acc[mt][nt];
#pragma unroll
                for (int h = 0; h < 2; h++) {
                    int r = r0 + h * 8;
                    float v0 = ac[h * 2], v1 = ac[h * 2 + 1];
                    size_t off = (size_t)r * DD + c0;
                    if (md == 4) {
                        float zr = 1.0f / Zv[r];
                        *(__half2*)(outH + off) = __floats2half2_rn(v0 * zr, v1 * zr);
                    } else if (md == 1) {
                        v0 += bb1[c0] + bb2[c0];
                        v1 += bb1[c0 + 1] + bb2[c0 + 1];
                        float s0 = 1.0f / (1.0f + __expf(-v0));
                        float s1 = 1.0f / (1.0f + __expf(-v1));
                        *(float2*)(outF + off) = make_float2(s0, s1);
                    } else if (md == 2) {
                        v0 += bb1[c0] + bb2[c0];
                        v1 += bb1[c0 + 1] + bb2[c0 + 1];
                        float s0 = (1.0f / (1.0f + __expf(-v0))) * X[off];
                        float s1 = (1.0f / (1.0f + __expf(-v1))) * X[off + 1];
                        *(__half2*)(outH2 + off) = __floats2half2_rn(s0, s1);
                    } else {
                        v0 += bb1[c0] + bb2[c0];
                        v1 += bb1[c0 + 1] + bb2[c0 + 1];
                        float t0 = fast_tanh(v0), t1 = fast_tanh(v1);
                        float u0 = U[off], u1 = U[off + 1];
                        float x0 = X[off], x1 = X[off + 1];
                        *(float2*)(outF + off) =
                            make_float2(x0 + u0 * (t0 - x0), x1 + u1 * (t1 - x1));
                    }
                }
            }
        }
    }

    // ---------------- producer signal ----------------
    if (prod_kind) {
        __syncthreads();
        __threadfence();
        if (tid == 0)
            atomicAdd(cnt_ptr(prod_kind, blockIdx.x, blockIdx.y, m0), 1);
    }
}

// ---------------- launch ----------------
extern "C" void kernel_launch(void* const* d_in, const int* in_sizes, int n_in,
                              void* d_out, int out_size)
{
    const float* inputs = (const float*)d_in[0];
    const float* adj    = (const float*)d_in[1];
    const float* W_fc   = (const float*)d_in[2];
    const float* b_fc   = (const float*)d_in[3];
    const float* w_q    = (const float*)d_in[4];
    const float* b_q    = (const float*)d_in[5];
    const float* w_k    = (const float*)d_in[6];
    const float* b_k    = (const float*)d_in[7];
    const float* W_uy   = (const float*)d_in[8];
    const float* b_uy   = (const float*)d_in[9];
    const float* W_ux   = (const float*)d_in[10];
    const float* b_ux   = (const float*)d_in[11];
    const float* W_ry   = (const float*)d_in[12];
    const float* b_ry   = (const float*)d_in[13];
    const float* W_rx   = (const float*)d_in[14];
    const float* b_rx   = (const float*)d_in[15];
    const float* W_ty   = (const float*)d_in[16];
    const float* b_ty   = (const float*)d_in[17];
    const float* W_tx   = (const float*)d_in[18];
    const float* b_tx   = (const float*)d_in[19];
    float* out = (float*)d_out;

    __half *in_h, *W7, *fpT, *y, *rx, *E;
    float *u, *Z;
    cudaGetSymbolAddress((void**)&in_h, g_in_h);
    cudaGetSymbolAddress((void**)&W7, g_W7);
    cudaGetSymbolAddress((void**)&fpT, g_fpT);
    cudaGetSymbolAddress((void**)&y, g_y);
    cudaGetSymbolAddress((void**)&rx, g_rx);
    cudaGetSymbolAddress((void**)&u, g_u);
    cudaGetSymbolAddress((void**)&E, g_E);
    cudaGetSymbolAddress((void**)&Z, g_Z);

    const int WSZ = DD * DD;
    const size_t smem = NSTAGE * STAGE;   // 96KB
    cudaFuncSetAttribute(mma_gemm, cudaFuncAttributeMaxDynamicSharedMemorySize, (int)smem);

    static cudaStream_t s2 = nullptr;
    static cudaEvent_t evFork = nullptr, evJoin = nullptr;
    if (!s2) {
        cudaStreamCreateWithFlags(&s2, cudaStreamNonBlocking);
        cudaEventCreateWithFlags(&evFork, cudaEventDisableTiming);
        cudaEventCreateWithFlags(&evJoin, cudaEventDisableTiming);
    }

    // ---- fork: q/k/E chain on s2 (feeds only GEMM2) ----
    cudaEventRecord(evFork, 0);
    cudaStreamWaitEvent(s2, evFork, 0);
    vqk_kernel<<<4, 256, 0, s2>>>(W_fc, w_q, w_k, b_fc, b_q, b_k);
    qk_kernel<<<MM, 256, 0, s2>>>(inputs);
    maskexp_kernel<<<MM, 256, 0, s2>>>(adj);
    cudaEventRecord(evJoin, s2);

    // ---- main stream: one merged convert launch (also zeroes counters) ----
    {
        int totalN4 = MM * DD / 4 + 7 * (WSZ / 4);
        cvt_all_kernel<<<(totalN4 + 255) / 256, 256>>>(
            inputs, W_fc, W_uy, W_ux, W_ry, W_rx, W_ty, W_tx, in_h, W7);
    }
    __half* Wfc_h = W7;
    __half* Wuy_h = W7 + (size_t)1 * WSZ;
    __half* Wux_h = W7 + (size_t)2 * WSZ;
    __half* Wry_h = W7 + (size_t)3 * WSZ;
    __half* Wrx_h = W7 + (size_t)4 * WSZ;
    __half* Wty_h = W7 + (size_t)5 * WSZ;
    __half* Wtx_h = W7 + (size_t)6 * WSZ;

    dim3 grid(DD / 128, MM / 128);       // (6, 128)
    dim3 gridZ(DD / 128, MM / 128, 2);   // merged u+rx

    cudaLaunchAttribute pdlAttr[1];
    pdlAttr[0].id = cudaLaunchAttributeProgrammaticStreamSerialization;
    pdlAttr[0].val.programmaticStreamSerializationAllowed = 1;

    auto launch_gemm = [&](dim3 g,
                           const __half* A1, const __half* B1,
                           const __half* A2, const __half* B2,
                           const __half* B1b, const __half* B2b,
                           const float* b1, const float* b2,
                           const float* b1b, const float* b2b,
                           const float* X, const float* U, const float* Zv,
                           float* outF, __half* outH, __half* outH2,
                           int K, int K1, int lda, int ldb, size_t bstrideB,
                           int mode, int rot,
                           int w0k, int w0t, int wBp, int wBk, int wBt, int prod) {
        cudaLaunchConfig_t cfg = {};
        cfg.gridDim = g;
        cfg.blockDim = dim3(256, 1, 1);
        cfg.dynamicSmemBytes = smem;
        cfg.stream = 0;
        cfg.attrs = pdlAttr;
        cfg.numAttrs = 1;
        cudaLaunchKernelEx(&cfg, mma_gemm,
                           A1, B1, A2, B2, B1b, B2b, b1, b2, b1b, b2b,
                           X, U, Zv, outF, outH, outH2,
                           K, K1, lda, ldb, bstrideB, mode, rot,
                           w0k, w0t, wBp, wBk, wBt, prod);
    };

    // 1) feat_proj -> fpT. PDL fallback = waits cvt completion; signals cntFp.
    launch_gemm(grid,
                in_h, Wfc_h, in_h, Wfc_h, nullptr, nullptr,
                b_fc, nullptr, nullptr, nullptr,
                nullptr, nullptr, nullptr,
                nullptr, fpT, nullptr,
                DD, DD, DD, DD, 0, 0, 0,
                0, 0, -1, 0, 0, 1);

    // ---- join: GEMM2 needs E/Z from s2 (stream edge) ----
    cudaStreamWaitEvent(0, evJoin, 0);

    // 2) y = (E @ fpT^T)/Z. Waits its 8 fpT producers (cntFp) at pos 0; signals cntY.
    launch_gemm(grid,
                E, fpT, E, fpT, nullptr, nullptr,
                nullptr, nullptr, nullptr, nullptr,
                nullptr, nullptr, Z,
                nullptr, y, nullptr,
                NN, NN, NN, NN, (size_t)DD * NN, 4, 0,
                1, 8, -1, 0, 0, 2);

    // 3+4) merged gates. rot=12: x-half (tiles 12..23) first — safe (cvt done before
    //      GEMM1 started); waits cntY[mb]==6 before y-half at pos 12; signals cntG.
    launch_gemm(gridZ,
                y, Wuy_h, in_h, Wux_h, Wry_h, Wrx_h,
                b_uy, b_ux, b_ry, b_rx,
                inputs, nullptr, nullptr,
                u, nullptr, rx,
                2 * DD, DD, DD, DD, 0, 5, 12,
                0, 0, 12, 2, 6, 3);

    // 5) final. y-half first after cntY[mb]==6; waits cntG[mb]==12 (rx AND u) at pos 12.
    launch_gemm(grid,
                y, Wty_h, rx, Wtx_h, nullptr, nullptr,
                b_ty, b_tx, nullptr, nullptr,
                inputs, u, nullptr,
                out, nullptr, nullptr,
                2 * DD, DD, DD, DD, 0, 3, 0,
                2, 6, 12, 3, 12, 0);
}

// round 17
// speedup vs baseline: 1.0613x; 1.0266x over previous
#include <cuda_runtime.h>
#include <cuda_fp16.h>
#include <cstdint>
#include <math.h>

#define NB 16
#define NN 1024
#define DD 768
#define MM (NB * NN)

// ---------------- scratch ----------------
__device__ __half g_in_h[(size_t)MM * DD];
__device__ __half g_W7[(size_t)7 * DD * DD];   // Wfc, Wuy, Wux, Wry, Wrx, Wty, Wtx
__device__ __half g_fpT[(size_t)NB * DD * NN];
__device__ __half g_y[(size_t)MM * DD];
__device__ __half g_rx[(size_t)MM * DD];
__device__ float  g_u[(size_t)MM * DD];
__device__ __half g_E[(size_t)NB * NN * NN];
__device__ float  g_Z[MM];
__device__ float  g_q[MM], g_k[MM];
__device__ float  g_vq[DD], g_vk[DD], g_cqk[2];

// readiness counters (tile-granular producer/consumer sync)
__device__ int g_cntFp[96];    // [b*6 + dblock], target 8  (GEMM1 -> GEMM2)
__device__ int g_cntY[128];    // [mblock],       target 6  (GEMM2 -> gates/final)
__device__ int g_cntG[128];    // [mblock],       target 12 (gates -> final)

// ---------------- PDL helper ----------------
__device__ __forceinline__ void pdl_trigger() {
#if __CUDA_ARCH__ >= 900
    cudaTriggerProgrammaticLaunchCompletion();
#endif
}

// ---------------- counter helpers ----------------
// kinds: 1 = Fp (idx b*6+bx), 2 = Y (idx by), 3 = G (idx by)
__device__ __forceinline__ int* cnt_ptr(int kind, int bx, int by, int m0) {
    if (kind == 1) return &g_cntFp[(m0 >> 10) * 6 + bx];
    if (kind == 2) return &g_cntY[by];
    return &g_cntG[by];
}

__device__ __forceinline__ void wait_cnt(int* c, int target) {
    if (threadIdx.x == 0) {
        while (atomicAdd(c, 0) < target) __nanosleep(64);
    }
    __syncthreads();
}

// ---------------- all fp32->fp16 converts in ONE launch (+ counter zeroing) ----------------
// 4 strided float4 per thread for MLP=4
#define CVT_TOTAL4 (MM * DD / 4 + 7 * (DD * DD / 4))   // 4177920 / 4-elem units... (per-index units)
#define CVT_SPAN   (CVT_TOTAL4 / 4)                    // 1044480 indices per rep

__global__ __launch_bounds__(256) void cvt_all_kernel(
    const float* __restrict__ inp,
    const float* __restrict__ w0, const float* __restrict__ w1,
    const float* __restrict__ w2, const float* __restrict__ w3,
    const float* __restrict__ w4, const float* __restrict__ w5,
    const float* __restrict__ w6,
    __half* __restrict__ in_h, __half* __restrict__ W7)
{
    if (blockIdx.x == 0) {
        int t = threadIdx.x;
        if (t < 96) g_cntFp[t] = 0;
        if (t < 128) { g_cntY[t] = 0; g_cntG[t] = 0; }
    }
    const int inN4 = MM * DD / 4;
    const int wN4 = DD * DD / 4;
    int base = blockIdx.x * 256 + threadIdx.x;
#pragma unroll
    for (int rep = 0; rep < 4; rep++) {
        int i = base + rep * CVT_SPAN;
        const float* src;
        __half* dst;
        int idx;
        if (i < inN4) {
            src = inp; dst = in_h; idx = i;
        } else {
            int j = i - inN4;
            if (j >= 7 * wN4) continue;
            int wi = j / wN4;
            idx = j - wi * wN4;
            switch (wi) {
                case 0: src = w0; break;
                case 1: src = w1; break;
                case 2: src = w2; break;
                case 3: src = w3; break;
                case 4: src = w4; break;
                case 5: src = w5; break;
                default: src = w6; break;
            }
            dst = W7 + (size_t)wi * DD * DD;
        }
        float4 v = ((const float4*)src)[idx];
        ((__half2*)dst)[idx * 2]     = __floats2half2_rn(v.x, v.y);
        ((__half2*)dst)[idx * 2 + 1] = __floats2half2_rn(v.z, v.w);
    }
}

// ---------------- vq/vk (blocks 0..2) + cqk (block 3) in one launch ----------------
__global__ __launch_bounds__(256) void vqk_kernel(
    const float* __restrict__ W_fc, const float* __restrict__ wq,
    const float* __restrict__ wk,
    const float* __restrict__ b_fc, const float* __restrict__ bq,
    const float* __restrict__ bk)
{
    if (blockIdx.x < 3) {
        int d = blockIdx.x * 256 + threadIdx.x;
        float sq = 0.0f, sk = 0.0f;
#pragma unroll 8
        for (int e = 0; e < DD; e++) {
            float w = W_fc[(size_t)e * DD + d];
            sq = fmaf(wq[e], w, sq);
            sk = fmaf(wk[e], w, sk);
        }
        g_vq[d] = sq;
        g_vk[d] = sk;
    } else {
        int tid = threadIdx.x;
        float sq = 0.0f, sk = 0.0f;
        for (int e = tid; e < DD; e += 256) {
            float b = b_fc[e];
            sq = fmaf(wq[e], b, sq);
            sk = fmaf(wk[e], b, sk);
        }
#pragma unroll
        for (int o = 16; o; o >>= 1) {
            sq += __shfl_down_sync(0xFFFFFFFFu, sq, o);
            sk += __shfl_down_sync(0xFFFFFFFFu, sk, o);
        }
        __shared__ float rq[8], rk[8];
        if ((tid & 31) == 0) { rq[tid >> 5] = sq; rk[tid >> 5] = sk; }
        __syncthreads();
        if (tid == 0) {
            float a = 0.0f, c = 0.0f;
#pragma unroll
            for (int w = 0; w < 8; w++) { a += rq[w]; c += rk[w]; }
            g_cqk[0] = a + bq[0];
            g_cqk[1] = c + bk[0];
        }
    }
}

// ---------------- q/k per-row dots (exact fp32) ----------------
__global__ __launch_bounds__(256) void qk_kernel(const float* __restrict__ inputs)
{
    const int m = blockIdx.x;
    const float* row = inputs + (size_t)m * DD;
    const int tid = threadIdx.x;
    float sq = 0.0f, sk = 0.0f;
    for (int d = tid; d < DD; d += 256) {
        float v = row[d];
        sq = fmaf(v, g_vq[d], sq);
        sk = fmaf(v, g_vk[d], sk);
    }
#pragma unroll
    for (int o = 16; o; o >>= 1) {
        sq += __shfl_down_sync(0xFFFFFFFFu, sq, o);
        sk += __shfl_down_sync(0xFFFFFFFFu, sk, o);
    }
    __shared__ float rq[8], rk[8];
    if ((tid & 31) == 0) { rq[tid >> 5] = sq; rk[tid >> 5] = sk; }
    __syncthreads();
    if (tid == 0) {
        float a = 0.0f, c = 0.0f;
#pragma unroll
        for (int w = 0; w < 8; w++) { a += rq[w]; c += rk[w]; }
        g_q[m] = a + g_cqk[0];
        g_k[m] = c + g_cqk[1];
    }
}

// ---------------- E = adj * exp(lrelu(q+k)) fp16 + exact row sums ----------------
__global__ __launch_bounds__(256) void maskexp_kernel(const float* __restrict__ adj)
{
    const int row = blockIdx.x;
    const int b = row >> 10;
    const float qi = g_q[row];
    const float* arow = adj + (size_t)row * NN;
    const float* kb = g_k + b * NN;
    __half* er = g_E + (size_t)row * NN;

    const int j4 = threadIdx.x;
    float4 a = ((const float4*)arow)[j4];
    float4 kv = ((const float4*)kb)[j4];
    float e[4];
    float vr[4] = {qi + kv.x, qi + kv.y, qi + kv.z, qi + kv.w};
    float ad[4] = {a.x, a.y, a.z, a.w};
#pragma unroll
    for (int t = 0; t < 4; t++) {
        float v = vr[t];
        float lr = v >= 0.0f ? v : 0.01f * v;
        e[t] = (ad[t] > 0.5f) ? __expf(lr) : 0.0f;
    }
    ((__half2*)er)[j4 * 2]     = __floats2half2_rn(e[0], e[1]);
    ((__half2*)er)[j4 * 2 + 1] = __floats2half2_rn(e[2], e[3]);

    float s = (e[0] + e[1]) + (e[2] + e[3]);
#pragma unroll
    for (int o = 16; o; o >>= 1) s += __shfl_down_sync(0xFFFFFFFFu, s, o);
    __shared__ float red[8];
    if ((threadIdx.x & 31) == 0) red[threadIdx.x >> 5] = s;
    __syncthreads();
    if (threadIdx.x == 0) {
        float t = 0.0f;
#pragma unroll
        for (int w = 0; w < 8; w++) t += red[w];
        g_Z[row] = t;
    }
}

// ================= fp16 1-pass MMA GEMM (PDL + counter sync, 3-stage) =================
#define TILE_B 16384
#define STAGE (2 * TILE_B)
#define NSTAGE 3

__device__ __forceinline__ uint32_t sw_off(int r, int c) {
    return (uint32_t)(r * 128 + ((c ^ (r & 7)) << 4));
}

__device__ __forceinline__ void ldsm4(uint32_t addr, uint32_t& r0, uint32_t& r1,
                                      uint32_t& r2, uint32_t& r3) {
    asm volatile("ldmatrix.sync.aligned.m8n8.x4.shared.b16 {%0,%1,%2,%3}, [%4];"
                 : "=r"(r0), "=r"(r1), "=r"(r2), "=r"(r3) : "r"(addr));
}

__device__ __forceinline__ void mma16(float* c, const uint32_t* a, const uint32_t* b) {
    asm volatile(
        "mma.sync.aligned.m16n8k16.row.col.f32.f16.f16.f32 "
        "{%0,%1,%2,%3}, {%4,%5,%6,%7}, {%8,%9}, {%0,%1,%2,%3};"
        : "+f"(c[0]), "+f"(c[1]), "+f"(c[2]), "+f"(c[3])
        : "r"(a[0]), "r"(a[1]), "r"(a[2]), "r"(a[3]), "r"(b[0]), "r"(b[1]));
}

__device__ __forceinline__ void cp16(char* smem_dst, const void* gsrc) {
    uint32_t s = (uint32_t)__cvta_generic_to_shared(smem_dst);
    asm volatile("cp.async.cg.shared.global [%0], [%1], 16;" :: "r"(s), "l"(gsrc));
}

// fast tanh via __expf; rel err ~1e-6
__device__ __forceinline__ float fast_tanh(float v) {
    float av = fabsf(v);
    float t = __expf(-2.0f * av);
    float th = __fdividef(1.0f - t, 1.0f + t);
    return copysignf(th, v);
}

__global__ __launch_bounds__(256, 2) void mma_gemm(
    const __half* __restrict__ A1, const __half* __restrict__ B1,
    const __half* __restrict__ A2, const __half* __restrict__ B2,
    const __half* __restrict__ B1b, const __half* __restrict__ B2b,
    const float* __restrict__ b1, const float* __restrict__ b2,
    const float* __restrict__ b1b, const float* __restrict__ b2b,
    const __half* __restrict__ Xh, const float* __restrict__ U,
    const float* __restrict__ Zv,
    float* __restrict__ outF, __half* __restrict__ outH, __half* __restrict__ outH2,
    int K, int K1, int lda, int ldb, size_t bstrideB, int mode,
    int rot,
    int w0_kind, int w0_target,
    int wB_pos, int wB_kind, int wB_target,
    int prod_kind)
{
    extern __shared__ char smem[];

    pdl_trigger();

    const int tid = threadIdx.x;
    const int lane = tid & 31;
    const int warp = tid >> 5;
    const int wy = warp >> 1;
    const int wx = warp & 1;
    const int m0 = blockIdx.y * 128;
    const int n0 = blockIdx.x * 128;

    const __half* Bw1 = B1;
    const __half* Bw2 = B2;
    const float* bb1 = b1;
    const float* bb2 = b2;
    int md = mode;
    if (mode == 5) {
        if (blockIdx.z == 1) { Bw1 = B1b; Bw2 = B2b; bb1 = b1b; bb2 = b2b; md = 2; }
        else md = 1;
    }

    const size_t bOffB = (size_t)(m0 >> 10) * bstrideB;

    const int lr = tid >> 1;
    const int lc4 = (tid & 1) * 4;

    float acc[2][8][4];
#pragma unroll
    for (int mt = 0; mt < 2; mt++)
#pragma unroll
        for (int nt = 0; nt < 8; nt++)
#pragma unroll
            for (int v = 0; v < 4; v++) acc[mt][nt][v] = 0.0f;

    const int NT = K / 64;

    auto load_tile = [&](int ktp, int st) {
        int kb = ktp * 64;
        const __half *A, *B;
        int ko;
        if (kb < K1) { A = A1; B = Bw1; ko = kb; }
        else         { A = A2; B = Bw2; ko = kb - K1; }
        char* base = smem + st * STAGE;
        size_t abase = (size_t)(m0 + lr) * lda + ko;
        size_t bbase = bOffB + (size_t)(n0 + lr) * ldb + ko;
#pragma unroll
        for (int c = 0; c < 4; c++) {
            int ch = lc4 + c;
            uint32_t so = sw_off(lr, ch);
            cp16(base + so,          A + abase + ch * 8);
            cp16(base + TILE_B + so, B + bbase + ch * 8);
        }
    };
    auto phys = [&](int pos) { int p = pos + rot; return p >= NT ? p - NT : p; };

    // prologue: tiles 0,1
    if (w0_kind) wait_cnt(cnt_ptr(w0_kind, blockIdx.x, blockIdx.y, m0), w0_target);
    load_tile(phys(0), 0);
    asm volatile("cp.async.commit_group;");
    if (NT > 1) load_tile(phys(1), 1);
    asm volatile("cp.async.commit_group;");

    for (int kt = 0; kt < NT; kt++) {
        asm volatile("cp.async.wait_group 1;");
        __syncthreads();
        if (kt + 2 < NT) {
            if (kt + 2 == wB_pos)
                wait_cnt(cnt_ptr(wB_kind, blockIdx.x, blockIdx.y, m0), wB_target);
            load_tile(phys(kt + 2), (kt + 2) % NSTAGE);
        }
        asm volatile("cp.async.commit_group;");

        char* As = smem + (kt % NSTAGE) * STAGE;
        char* Bs = As + TILE_B;

#pragma unroll
        for (int ks = 0; ks < 4; ks++) {
            uint32_t ah[2][4], bh[8][2];
#pragma unroll
            for (int mt = 0; mt < 2; mt++) {
                int r = wy * 32 + mt * 16 + (lane & 15);
                int ch = ks * 2 + (lane >> 4);
                uint32_t so = sw_off(r, ch);
                ldsm4((uint32_t)__cvta_generic_to_shared(As + so),
                      ah[mt][0], ah[mt][1], ah[mt][2], ah[mt][3]);
            }
#pragma unroll
            for (int np = 0; np < 4; np++) {
                int r = wx * 64 + np * 16 + (lane & 7) + ((lane >> 4) << 3);
                int ch = ks * 2 + ((lane >> 3) & 1);
                uint32_t so = sw_off(r, ch);
                ldsm4((uint32_t)__cvta_generic_to_shared(Bs + so),
                      bh[np * 2][0], bh[np * 2][1], bh[np * 2 + 1][0], bh[np * 2 + 1][1]);
            }
#pragma unroll
            for (int mt = 0; mt < 2; mt++)
#pragma unroll
                for (int nt = 0; nt < 8; nt++)
                    mma16(acc[mt][nt], ah[mt], bh[nt]);
        }
    }

    // ---------------- epilogue ----------------
    if (md == 0) {
        __syncthreads();   // smem reuse for transpose
        __half* T = (__half*)smem + warp * (64 * 34);
#pragma unroll
        for (int mt = 0; mt < 2; mt++) {
#pragma unroll
            for (int nt = 0; nt < 8; nt++) {
                int c0l = nt * 8 + (lane & 3) * 2;
                int cg = n0 + wx * 64 + c0l;
                float* ac = acc[mt][nt];
#pragma unroll
                for (int h = 0; h < 2; h++) {
                    int rr = mt * 16 + (lane >> 2) + h * 8;
                    T[c0l * 34 + rr]       = __float2half(ac[h * 2]     + bb1[cg]);
                    T[(c0l + 1) * 34 + rr] = __float2half(ac[h * 2 + 1] + bb1[cg + 1]);
                }
            }
        }
        __syncwarp();
        const int bb = m0 >> 10;
        const int jj0 = (m0 & 1023) + wy * 32;
#pragma unroll
        for (int cp = 0; cp < 2; cp++) {
            int c = lane + cp * 32;
            const uint32_t* src = (const uint32_t*)(T + c * 34);
            uint32_t w4[16];
#pragma unroll
            for (int i = 0; i < 16; i++) w4[i] = src[i];
            size_t g = ((size_t)bb * DD + (n0 + wx * 64 + c)) * NN + jj0;
            uint4* dst = (uint4*)(outH + g);
            dst[0] = make_uint4(w4[0],  w4[1],  w4[2],  w4[3]);
            dst[1] = make_uint4(w4[4],  w4[5],  w4[6],  w4[7]);
            dst[2] = make_uint4(w4[8],  w4[9],  w4[10], w4[11]);
            dst[3] = make_uint4(w4[12], w4[13], w4[14], w4[15]);
        }
    } else {
        const int mbase = m0 + wy * 32;
        const int nbase = n0 + wx * 64;
#pragma unroll
        for (int mt = 0; mt < 2; mt++) {
#pragma unroll
            for (int nt = 0; nt < 8; nt++) {
                int c0 = nbase + nt * 8 + (lane & 3) * 2;
                int r0 = mbase + mt * 16 + (lane >> 2);
                float* ac = acc[mt][nt];
#pragma unroll
                for (int h = 0; h < 2; h++) {
                    int r = r0 + h * 8;
                    float v0 = ac[h * 2], v1 = ac[h * 2 + 1];
                    size_t off = (size_t)r * DD + c0;
                    if (md == 4) {
                        float zr = 1.0f / Zv[r];
                        *(__half2*)(outH + off) = __floats2half2_rn(v0 * zr, v1 * zr);
                    } else if (md == 1) {
                        v0 += bb1[c0] + bb2[c0];
                        v1 += bb1[c0 + 1] + bb2[c0 + 1];
                        float s0 = 1.0f / (1.0f + __expf(-v0));
                        float s1 = 1.0f / (1.0f + __expf(-v1));
                        *(float2*)(outF + off) = make_float2(s0, s1);
                    } else if (md == 2) {
                        v0 += bb1[c0] + bb2[c0];
                        v1 += bb1[c0 + 1] + bb2[c0 + 1];
                        __half2 xp = *(const __half2*)(Xh + off);
                        float s0 = (1.0f / (1.0f + __expf(-v0))) * __low2float(xp);
                        float s1 = (1.0f / (1.0f + __expf(-v1))) * __high2float(xp);
                        *(__half2*)(outH2 + off) = __floats2half2_rn(s0, s1);
                    } else {
                        v0 += bb1[c0] + bb2[c0];
                        v1 += bb1[c0 + 1] + bb2[c0 + 1];
                        float t0 = fast_tanh(v0), t1 = fast_tanh(v1);
                        float u0 = U[off], u1 = U[off + 1];
                        __half2 xp = *(const __half2*)(Xh + off);
                        float x0 = __low2float(xp), x1 = __high2float(xp);
                        *(float2*)(outF + off) =
                            make_float2(x0 + u0 * (t0 - x0), x1 + u1 * (t1 - x1));
                    }
                }
            }
        }
    }

    // ---------------- producer signal ----------------
    if (prod_kind) {
        __syncthreads();
        __threadfence();
        if (tid == 0)
            atomicAdd(cnt_ptr(prod_kind, blockIdx.x, blockIdx.y, m0), 1);
    }
}

// ---------------- launch ----------------
extern "C" void kernel_launch(void* const* d_in, const int* in_sizes, int n_in,
                              void* d_out, int out_size)
{
    const float* inputs = (const float*)d_in[0];
    const float* adj    = (const float*)d_in[1];
    const float* W_fc   = (const float*)d_in[2];
    const float* b_fc   = (const float*)d_in[3];
    const float* w_q    = (const float*)d_in[4];
    const float* b_q    = (const float*)d_in[5];
    const float* w_k    = (const float*)d_in[6];
    const float* b_k    = (const float*)d_in[7];
    const float* W_uy   = (const float*)d_in[8];
    const float* b_uy   = (const float*)d_in[9];
    const float* W_ux   = (const float*)d_in[10];
    const float* b_ux   = (const float*)d_in[11];
    const float* W_ry   = (const float*)d_in[12];
    const float* b_ry   = (const float*)d_in[13];
    const float* W_rx   = (const float*)d_in[14];
    const float* b_rx   = (const float*)d_in[15];
    const float* W_ty   = (const float*)d_in[16];
    const float* b_ty   = (const float*)d_in[17];
    const float* W_tx   = (const float*)d_in[18];
    const float* b_tx   = (const float*)d_in[19];
    float* out = (float*)d_out;

    __half *in_h, *W7, *fpT, *y, *rx, *E;
    float *u, *Z;
    cudaGetSymbolAddress((void**)&in_h, g_in_h);
    cudaGetSymbolAddress((void**)&W7, g_W7);
    cudaGetSymbolAddress((void**)&fpT, g_fpT);
    cudaGetSymbolAddress((void**)&y, g_y);
    cudaGetSymbolAddress((void**)&rx, g_rx);
    cudaGetSymbolAddress((void**)&u, g_u);
    cudaGetSymbolAddress((void**)&E, g_E);
    cudaGetSymbolAddress((void**)&Z, g_Z);

    const int WSZ = DD * DD;
    const size_t smem = NSTAGE * STAGE;   // 96KB
    cudaFuncSetAttribute(mma_gemm, cudaFuncAttributeMaxDynamicSharedMemorySize, (int)smem);

    static cudaStream_t s2 = nullptr;
    static cudaEvent_t evFork = nullptr, evJoin = nullptr;
    if (!s2) {
        cudaStreamCreateWithFlags(&s2, cudaStreamNonBlocking);
        cudaEventCreateWithFlags(&evFork, cudaEventDisableTiming);
        cudaEventCreateWithFlags(&evJoin, cudaEventDisableTiming);
    }

    // ---- fork: q/k/E chain on s2 (feeds only GEMM2) ----
    cudaEventRecord(evFork, 0);
    cudaStreamWaitEvent(s2, evFork, 0);
    vqk_kernel<<<4, 256, 0, s2>>>(W_fc, w_q, w_k, b_fc, b_q, b_k);
    qk_kernel<<<MM, 256, 0, s2>>>(inputs);
    maskexp_kernel<<<MM, 256, 0, s2>>>(adj);
    cudaEventRecord(evJoin, s2);

    // ---- main stream: one merged convert launch (also zeroes counters) ----
    cvt_all_kernel<<<CVT_SPAN / 256, 256>>>(
        inputs, W_fc, W_uy, W_ux, W_ry, W_rx, W_ty, W_tx, in_h, W7);
    __half* Wfc_h = W7;
    __half* Wuy_h = W7 + (size_t)1 * WSZ;
    __half* Wux_h = W7 + (size_t)2 * WSZ;
    __half* Wry_h = W7 + (size_t)3 * WSZ;
    __half* Wrx_h = W7 + (size_t)4 * WSZ;
    __half* Wty_h = W7 + (size_t)5 * WSZ;
    __half* Wtx_h = W7 + (size_t)6 * WSZ;

    dim3 grid(DD / 128, MM / 128);       // (6, 128)
    dim3 gridZ(DD / 128, MM / 128, 2);   // merged u+rx

    cudaLaunchAttribute pdlAttr[1];
    pdlAttr[0].id = cudaLaunchAttributeProgrammaticStreamSerialization;
    pdlAttr[0].val.programmaticStreamSerializationAllowed = 1;

    auto launch_gemm = [&](dim3 g,
                           const __half* A1, const __half* B1,
                           const __half* A2, const __half* B2,
                           const __half* B1b, const __half* B2b,
                           const float* b1, const float* b2,
                           const float* b1b, const float* b2b,
                           const __half* Xh, const float* U, const float* Zv,
                           float* outF, __half* outH, __half* outH2,
                           int K, int K1, int lda, int ldb, size_t bstrideB,
                           int mode, int rot,
                           int w0k, int w0t, int wBp, int wBk, int wBt, int prod) {
        cudaLaunchConfig_t cfg = {};
        cfg.gridDim = g;
        cfg.blockDim = dim3(256, 1, 1);
        cfg.dynamicSmemBytes = smem;
        cfg.stream = 0;
        cfg.attrs = pdlAttr;
        cfg.numAttrs = 1;
        cudaLaunchKernelEx(&cfg, mma_gemm,
                           A1, B1, A2, B2, B1b, B2b, b1, b2, b1b, b2b,
                           Xh, U, Zv, outF, outH, outH2,
                           K, K1, lda, ldb, bstrideB, mode, rot,
                           w0k, w0t, wBp, wBk, wBt, prod);
    };

    // 1) feat_proj -> fpT. PDL fallback = waits cvt completion; signals cntFp.
    launch_gemm(grid,
                in_h, Wfc_h, in_h, Wfc_h, nullptr, nullptr,
                b_fc, nullptr, nullptr, nullptr,
                nullptr, nullptr, nullptr,
                nullptr, fpT, nullptr,
                DD, DD, DD, DD, 0, 0, 0,
                0, 0, -1, 0, 0, 1);

    // ---- join: GEMM2 needs E/Z from s2 (stream edge) ----
    cudaStreamWaitEvent(0, evJoin, 0);

    // 2) y = (E @ fpT^T)/Z. Waits its 8 fpT producers (cntFp) at pos 0; signals cntY.
    launch_gemm(grid,
                E, fpT, E, fpT, nullptr, nullptr,
                nullptr, nullptr, nullptr, nullptr,
                nullptr, nullptr, Z,
                nullptr, y, nullptr,
                NN, NN, NN, NN, (size_t)DD * NN, 4, 0,
                1, 8, -1, 0, 0, 2);

    // 3+4) merged gates. rot=12: x-half (tiles 12..23) first — safe (cvt done before
    //      GEMM1 started); waits cntY[mb]==6 before y-half at pos 12; signals cntG.
    launch_gemm(gridZ,
                y, Wuy_h, in_h, Wux_h, Wry_h, Wrx_h,
                b_uy, b_ux, b_ry, b_rx,
                in_h, nullptr, nullptr,
                u, nullptr, rx,
                2 * DD, DD, DD, DD, 0, 5, 12,
                0, 0, 12, 2, 6, 3);

    // 5) final. y-half first after cntY[mb]==6; waits cntG[mb]==12 (rx AND u) at pos 12.
    launch_gemm(grid,
                y, Wty_h, rx, Wtx_h, nullptr, nullptr,
                b_ty, b_tx, nullptr, nullptr,
                in_h, u, nullptr,
                out, nullptr, nullptr,
                2 * DD, DD, DD, DD, 0, 3, 0,
                2, 6, 12, 3, 12, 0);
}